// round 14
// baseline (speedup 1.0000x reference)
#include <cuda_runtime.h>
#include <math.h>

// ---------------- problem constants ----------------
#define NN    50000
#define FIN   256
#define FOUT  128
#define HH    128
#define DD    16
#define EE    (NN*DD)     // 800000
#define G4    512         // 4*H

// ---------------- scratch ----------------
__device__ float    g_proj[(size_t)NN*FOUT];   // 25.6MB
__device__ float    g_P2[(size_t)NN*G4];       // 102.4MB  P2 = proj @ w_ih^T (permuted cols)
__device__ float    g_ssrc[NN];
__device__ float    g_strg[NN];
__device__ int      g_seqsrc[EE];
__device__ float    g_seqatt[EE];
__device__ float    g_wih_p[G4*HH];            // permuted w_ih  [512 rows][128]
__device__ float    g_whh_pT[HH*G4];           // permuted w_hh  [128 k][512 cols] K-major
__device__ float    g_bcat[G4];

// ---------------- helpers ----------------
__device__ __forceinline__ float tanh_fast(float x) {
    float r;
    asm("tanh.approx.f32 %0, %1;" : "=f"(r) : "f"(x));
    return r;
}
__device__ __forceinline__ float sig_fast(float x) {
    return fmaf(tanh_fast(0.5f * x), 0.5f, 0.5f);
}
// packed f32x2 ops (Blackwell sm_103a)
typedef unsigned long long ull;
__device__ __forceinline__ ull pack2(float x, float y) {
    ull r; asm("mov.b64 %0, {%1,%2};" : "=l"(r) : "f"(x), "f"(y)); return r;
}
__device__ __forceinline__ float2 unpack2(ull v) {
    float2 r; asm("mov.b64 {%0,%1}, %2;" : "=f"(r.x), "=f"(r.y) : "l"(v)); return r;
}
__device__ __forceinline__ ull ffma2_(ull a, ull b, ull c) {
    ull d; asm("fma.rn.f32x2 %0, %1, %2, %3;" : "=l"(d) : "l"(a), "l"(b), "l"(c)); return d;
}
__device__ __forceinline__ ull add2_(ull a, ull b) {
    ull d; asm("add.rn.f32x2 %0, %1, %2;" : "=l"(d) : "l"(a), "l"(b)); return d;
}
// cp.async helpers
__device__ __forceinline__ void cp16(unsigned dst, const void* src) {
    asm volatile("cp.async.ca.shared.global [%0], [%1], 16;" :: "r"(dst), "l"(src));
}
__device__ __forceinline__ void cp_commit() { asm volatile("cp.async.commit_group;"); }
template <int N>
__device__ __forceinline__ void cp_wait() { asm volatile("cp.async.wait_group %0;" :: "n"(N)); }

// ---------------- kernel 1: prep + proj/skip GEMM + attention dots (fused) -------
__global__ __launch_bounds__(256) void gemm1_k(const float* __restrict__ x,
                                               const float* __restrict__ Wp,
                                               const float* __restrict__ Wsk,
                                               const float* __restrict__ asrc,
                                               const float* __restrict__ atrg,
                                               const float* __restrict__ wih,
                                               const float* __restrict__ whh,
                                               const float* __restrict__ bih,
                                               const float* __restrict__ bhh,
                                               float* __restrict__ out) {
    __shared__ float xs2[32 * 66];    // [kk][row] transposed, pad 2
    __shared__ float ws[256 * 33];    // [col][kk]
    int tid = threadIdx.x, lane = tid & 31, wrp = tid >> 5;
    int n0 = blockIdx.x * 64;

    // fused weight prep (one idx per thread in blocks 0..255)
    if (blockIdx.x < 256) {
        int idx = blockIdx.x * 256 + tid;   // 0..65535
        int R = idx >> 7;
        int k = idx & 127;
        int ch = R >> 7, c = R & 127;
        int gate = c >> 5, dd = c & 31;
        int grow = gate * 128 + ch * 32 + dd;
        g_wih_p[R * 128 + k]  = wih[grow * 128 + k];
        g_whh_pT[k * 512 + R] = whh[grow * 128 + k];
        if (k == 0) g_bcat[R] = bih[grow] + bhh[grow];
    }

    ull accp[4][8];
#pragma unroll
    for (int rp = 0; rp < 4; rp++)
#pragma unroll
        for (int j = 0; j < 8; j++) accp[rp][j] = 0ull;

    for (int k0 = 0; k0 < 256; k0 += 32) {
        __syncthreads();
#pragma unroll
        for (int v = 0; v < 8; v++) {
            int idx = tid + v * 256;
            int r = idx >> 5, kk = idx & 31;
            int n = n0 + r;
            xs2[kk * 66 + r] = (n < NN) ? x[(size_t)n * 256 + k0 + kk] : 0.0f;
        }
#pragma unroll
        for (int v = 0; v < 32; v++) {
            int idx = tid + v * 256;
            int c = idx >> 5, kk = idx & 31;
            ws[c * 33 + kk] = (c < 128) ? Wp[c * 256 + k0 + kk]
                                        : Wsk[(c - 128) * 256 + k0 + kk];
        }
        __syncthreads();
#pragma unroll 4
        for (int kk = 0; kk < 32; kk++) {
            ull uvp[4], wvp[8];
#pragma unroll
            for (int rp = 0; rp < 4; rp++) {
                float2 u2 = *(const float2*)(xs2 + kk * 66 + wrp * 8 + 2 * rp);
                uvp[rp] = pack2(u2.x, u2.y);
            }
#pragma unroll
            for (int j = 0; j < 8; j++) {
                float wv = ws[(j * 32 + lane) * 33 + kk];
                wvp[j] = pack2(wv, wv);
            }
#pragma unroll
            for (int rp = 0; rp < 4; rp++)
#pragma unroll
                for (int j = 0; j < 8; j++)
                    accp[rp][j] = ffma2_(uvp[rp], wvp[j], accp[rp][j]);
        }
    }

    // store proj/skip
#pragma unroll
    for (int rp = 0; rp < 4; rp++) {
        int n = n0 + wrp * 8 + 2 * rp;
#pragma unroll
        for (int j = 0; j < 8; j++) {
            float2 res = unpack2(accp[rp][j]);
            int c = j * 32 + lane;
            if (n < NN) {
                if (c < 128) g_proj[(size_t)n * 128 + c] = res.x;
                else         out[(size_t)n * 128 + (c - 128)] = res.x;
            }
            if (n + 1 < NN) {
                if (c < 128) g_proj[(size_t)(n + 1) * 128 + c] = res.y;
                else         out[(size_t)(n + 1) * 128 + (c - 128)] = res.y;
            }
        }
    }

    // fused attention dots: s_src/s_trg for the 8 rows (4 packed row-pairs)
    ull s1p[4], s2p[4];
#pragma unroll
    for (int rp = 0; rp < 4; rp++) { s1p[rp] = 0ull; s2p[rp] = 0ull; }
#pragma unroll
    for (int j = 0; j < 4; j++) {            // proj cols only (j*32+lane < 128)
        int c = j * 32 + lane;
        float av = asrc[c], tv = atrg[c];
        ull avp = pack2(av, av);
        ull tvp = pack2(tv, tv);
#pragma unroll
        for (int rp = 0; rp < 4; rp++) {
            s1p[rp] = ffma2_(accp[rp][j], avp, s1p[rp]);
            s2p[rp] = ffma2_(accp[rp][j], tvp, s2p[rp]);
        }
    }
#pragma unroll
    for (int rp = 0; rp < 4; rp++) {
#pragma unroll
        for (int o = 16; o; o >>= 1) {
            s1p[rp] = add2_(s1p[rp], __shfl_xor_sync(0xffffffffu, s1p[rp], o));
            s2p[rp] = add2_(s2p[rp], __shfl_xor_sync(0xffffffffu, s2p[rp], o));
        }
        if (lane == 0) {
            float2 v1 = unpack2(s1p[rp]);
            float2 v2 = unpack2(s2p[rp]);
            int n = n0 + wrp * 8 + 2 * rp;
            if (n < NN)     { g_ssrc[n] = v1.x;     g_strg[n] = v2.x; }
            if (n + 1 < NN) { g_ssrc[n + 1] = v1.y; g_strg[n + 1] = v2.y; }
        }
    }
}

// ---------------- kernel 2: P2 = proj @ w_ih_p^T (FFMA2, row-paired, K=128) ------
__global__ __launch_bounds__(256) void p2_k() {
    __shared__ float xs2[32 * 66];
    __shared__ float ws[256 * 33];
    int tid = threadIdx.x, lane = tid & 31, wrp = tid >> 5;
    int n0 = blockIdx.x * 64;
    int coff = blockIdx.y * 256;
    ull accp[4][8];
#pragma unroll
    for (int rp = 0; rp < 4; rp++)
#pragma unroll
        for (int j = 0; j < 8; j++) accp[rp][j] = 0ull;

    for (int k0 = 0; k0 < 128; k0 += 32) {
        __syncthreads();
#pragma unroll
        for (int v = 0; v < 8; v++) {
            int idx = tid + v * 256;
            int r = idx >> 5, kk = idx & 31;
            int n = n0 + r;
            xs2[kk * 66 + r] = (n < NN) ? g_proj[(size_t)n * 128 + k0 + kk] : 0.0f;
        }
#pragma unroll
        for (int v = 0; v < 32; v++) {
            int idx = tid + v * 256;
            int c = idx >> 5, kk = idx & 31;
            ws[c * 33 + kk] = g_wih_p[(coff + c) * 128 + k0 + kk];
        }
        __syncthreads();
#pragma unroll 4
        for (int kk = 0; kk < 32; kk++) {
            ull uvp[4], wvp[8];
#pragma unroll
            for (int rp = 0; rp < 4; rp++) {
                float2 u2 = *(const float2*)(xs2 + kk * 66 + wrp * 8 + 2 * rp);
                uvp[rp] = pack2(u2.x, u2.y);
            }
#pragma unroll
            for (int j = 0; j < 8; j++) {
                float wv = ws[(j * 32 + lane) * 33 + kk];
                wvp[j] = pack2(wv, wv);
            }
#pragma unroll
            for (int rp = 0; rp < 4; rp++)
#pragma unroll
                for (int j = 0; j < 8; j++)
                    accp[rp][j] = ffma2_(uvp[rp], wvp[j], accp[rp][j]);
        }
    }
#pragma unroll
    for (int rp = 0; rp < 4; rp++) {
        int n = n0 + wrp * 8 + 2 * rp;
#pragma unroll
        for (int j = 0; j < 8; j++) {
            float2 res = unpack2(accp[rp][j]);
            int c = coff + j * 32 + lane;
            if (n < NN)     g_P2[(size_t)n * 512 + c] = res.x;
            if (n + 1 < NN) g_P2[(size_t)(n + 1) * 512 + c] = res.y;
        }
    }
}

// ---------------- kernel 3: fused scores + softmax (per-node max) + sort ---------
__global__ void sortf_k(const int* __restrict__ ei) {
    int n = blockIdx.x * blockDim.x + threadIdx.x;
    if (n >= NN) return;
    int srcs[DD];
    float ev[DD], srt[DD];
    int idx[DD];
    float mx = -1e30f;
#pragma unroll
    for (int j = 0; j < DD; j++) {
        int e = n * DD + j;
        int s = ei[e];
        int t = ei[EE + e];
        srcs[j] = s;
        float v = g_ssrc[s] + g_strg[t];
        v = (v >= 0.0f) ? v : 0.2f * v;
        ev[j] = v;
        mx = fmaxf(mx, v);
    }
    float denom = 0.0f;
#pragma unroll
    for (int j = 0; j < DD; j++) {
        float e = expf(ev[j] - mx);
        ev[j] = e;
        denom += e;
    }
    denom += 1e-16f;
    for (int j = 0; j < DD; j++) {
        float key = ev[j];
        int pos = j;
        while (pos > 0 && srt[pos - 1] <= key) {
            srt[pos] = srt[pos - 1];
            idx[pos] = idx[pos - 1];
            pos--;
        }
        srt[pos] = key;
        idx[pos] = j;
    }
    float inv = 1.0f / denom;
#pragma unroll
    for (int t = 0; t < DD; t++) {
        g_seqsrc[n * DD + t] = srcs[idx[t]];
        g_seqatt[n * DD + t] = srt[t] * inv;
    }
}

// ---------------- kernel 4: backward LSTM, 512 threads / 16 warps -----------------
// Same aggregate traffic as the 256-thread version, but 4 warps/SMSP for latency
// hiding. Warp w: rows (w&7)*8..+8, chunks {2*(w>>3)+hl}. Each thread owns one
// dim-pair x all 4 gates -> accp[8][4], c in registers (creg2[8]).
// Continuous cross-timestep weight ring (2 buffers); seq data preloaded.
#define U_STR 132
#define KT 32
#define W_STR 520
#define LSTM_SM_FLOATS (64*U_STR + 2*KT*W_STR + 2*64*DD + 32)

__global__ __launch_bounds__(512, 1) void lstm_k(const float* __restrict__ bias,
                                                 float* __restrict__ out) {
    extern __shared__ float sm[];
    float* u    = sm;                          // [64][U_STR] h (in-place)
    float* wsm  = sm + 64 * U_STR;             // [2][KT][W_STR] w tile ring
    float* satt = wsm + 2 * KT * W_STR;        // [DD][64]
    int*   ssrc = (int*)(satt + 64 * DD);      // [DD][64]

    int tid = threadIdx.x, lane = tid & 31, wrp = tid >> 5;
    int rw = wrp & 7;                 // row group
    int chh = wrp >> 3;               // chunk half (0: chunks 0-1, 1: chunks 2-3)
    int hl = lane >> 4, p = lane & 15;
    int chunk = chh * 2 + hl;
    int n0 = blockIdx.x * 64;
    unsigned wsm_s = (unsigned)__cvta_generic_to_shared(wsm);

    // col offsets: gate g -> col = chunk*128 + g*32 + 2p
    int co[4];
#pragma unroll
    for (int g = 0; g < 4; g++) co[g] = chunk * 128 + g * 32 + 2 * p;

    // bias pairs
    ull bcp[4];
#pragma unroll
    for (int g = 0; g < 4; g++) {
        float2 b2 = *(const float2*)(g_bcat + co[g]);
        bcp[g] = pack2(b2.x, b2.y);
    }

    // cell state: creg2[row] = c for dims chunk*32 + {2p,2p+1}
    float2 creg2[8];
#pragma unroll
    for (int i = 0; i < 8; i++) creg2[i] = make_float2(0.0f, 0.0f);

    // preload ALL timesteps' seq data: layout [t][node]
#pragma unroll
    for (int v = 0; v < 2; v++) {
        int idx = tid + v * 512;             // 0..1023 = node*16 + t
        int node = idx >> 4, t = idx & 15;
        int n = n0 + node;
        if (n < NN) {
            ssrc[t * 64 + node] = g_seqsrc[n * DD + t];
            satt[t * 64 + node] = g_seqatt[n * DD + t];
        } else {
            ssrc[t * 64 + node] = 0;
            satt[t * 64 + node] = 0.0f;
        }
    }

    // weight ring prologue: issue tiles 0 and 1 (own commit groups)
#pragma unroll
    for (int tile = 0; tile < 2; tile++) {
        unsigned db = wsm_s + ((tile & 1) * KT * W_STR) * 4;
#pragma unroll
        for (int v = 0; v < 8; v++) {
            int f4 = tid + v * 512;
            int kk = f4 >> 7, c4 = f4 & 127;
            cp16(db + (kk * W_STR + c4 * 4) * 4,
                 g_whh_pT + (size_t)(tile * KT + kk) * 512 + c4 * 4);
        }
        cp_commit();
    }
    __syncthreads();   // seq data visible

#pragma unroll 1
    for (int t = 0; t < DD; t++) {
        ull accp[8][4];
#pragma unroll
        for (int i = 0; i < 8; i++)
#pragma unroll
            for (int g = 0; g < 4; g++) accp[i][g] = 0ull;

        if (t > 0) {
#pragma unroll 1
            for (int kt = 0; kt < 4; kt++) {
                cp_wait<1>();          // tile kt has landed (issued >=2 phases ago)
                __syncthreads();

                const float* wb = wsm + (kt & 1) * KT * W_STR;
                const float* ub = u + kt * KT;
#pragma unroll 4
                for (int kk2 = 0; kk2 < KT / 2; kk2++) {
                    float2 uk[8];
#pragma unroll
                    for (int i = 0; i < 8; i++)
                        uk[i] = *(const float2*)(ub + (rw * 8 + i) * U_STR + 2 * kk2);
#pragma unroll
                    for (int sub = 0; sub < 2; sub++) {
                        ull wvp[4];
#pragma unroll
                        for (int g = 0; g < 4; g++) {
                            float2 w2 = *(const float2*)(wb + (2 * kk2 + sub) * W_STR + co[g]);
                            wvp[g] = pack2(w2.x, w2.y);
                        }
#pragma unroll
                        for (int i = 0; i < 8; i++) {
                            float us = sub ? uk[i].y : uk[i].x;
                            ull up = pack2(us, us);
#pragma unroll
                            for (int g = 0; g < 4; g++)
                                accp[i][g] = ffma2_(up, wvp[g], accp[i][g]);
                        }
                    }
                }
                __syncthreads();

                // refill this buffer with the tile needed 2 phases from now
                {
                    int ntile = (kt + 2) & 3;
                    unsigned db = wsm_s + ((kt & 1) * KT * W_STR) * 4;
#pragma unroll
                    for (int v = 0; v < 8; v++) {
                        int f4 = tid + v * 512;
                        int kk = f4 >> 7, c4 = f4 & 127;
                        cp16(db + (kk * W_STR + c4 * 4) * 4,
                             g_whh_pT + (size_t)(ntile * KT + kk) * 512 + c4 * 4);
                    }
                    cp_commit();
                }
            }
        }

        // x-contribution: acc = acc + bias + att * P2[src]  (batched 2 rows)
        const float* sattT = satt + t * 64;
        const int*   ssrcT = ssrc + t * 64;
#pragma unroll
        for (int b = 0; b < 4; b++) {
            ull pvp[2][4];
#pragma unroll
            for (int i2 = 0; i2 < 2; i2++) {
                int s = ssrcT[rw * 8 + b * 2 + i2];
                const float* pp = g_P2 + (size_t)s * 512;
#pragma unroll
                for (int g = 0; g < 4; g++) {
                    float2 v2 = *(const float2*)(pp + co[g]);
                    pvp[i2][g] = pack2(v2.x, v2.y);
                }
            }
#pragma unroll
            for (int i2 = 0; i2 < 2; i2++) {
                int i = b * 2 + i2;
                float a = sattT[rw * 8 + i];
                ull ap = pack2(a, a);
#pragma unroll
                for (int g = 0; g < 4; g++)
                    accp[i][g] = ffma2_(ap, pvp[i2][g], add2_(accp[i][g], bcp[g]));
            }
        }

        // gate activations + c/h update (h written in place; all u reads done)
#pragma unroll
        for (int i = 0; i < 8; i++) {
            float2 iv = unpack2(accp[i][0]);
            float2 fv = unpack2(accp[i][1]);
            float2 gv = unpack2(accp[i][2]);
            float2 ov = unpack2(accp[i][3]);
            float2 cp2 = creg2[i];
            float c0 = fmaf(sig_fast(fv.x), cp2.x, sig_fast(iv.x) * tanh_fast(gv.x));
            float c1 = fmaf(sig_fast(fv.y), cp2.y, sig_fast(iv.y) * tanh_fast(gv.y));
            creg2[i] = make_float2(c0, c1);
            float2 hh = make_float2(sig_fast(ov.x) * tanh_fast(c0),
                                    sig_fast(ov.y) * tanh_fast(c1));
            *(float2*)(u + (rw * 8 + i) * U_STR + chunk * 32 + 2 * p) = hh;
        }
        __syncthreads();
    }

    // epilogue: final h in u
    for (int idx = tid; idx < 64 * 128; idx += 512) {
        int r = idx >> 7, d = idx & 127;
        int n = n0 + r;
        if (n < NN) {
            float v = u[r * U_STR + d] + out[(size_t)n * 128 + d] + bias[d];
            out[(size_t)n * 128 + d] = (v >= 0.0f) ? v : 0.01f * v;
        }
    }
}

// ---------------- launch ----------------
extern "C" void kernel_launch(void* const* d_in, const int* in_sizes, int n_in,
                              void* d_out, int out_size) {
    const float* x    = (const float*)d_in[0];
    const float* Wp   = (const float*)d_in[1];
    const float* asrc = (const float*)d_in[2];
    const float* atrg = (const float*)d_in[3];
    const float* Wsk  = (const float*)d_in[4];
    const float* bias = (const float*)d_in[5];
    // d_in[6..9]: forward-direction weights, unused by the reference
    const float* wihb = (const float*)d_in[10];
    const float* whhb = (const float*)d_in[11];
    const float* bihb = (const float*)d_in[12];
    const float* bhhb = (const float*)d_in[13];
    const int*   ei   = (const int*)d_in[14];
    float* out = (float*)d_out;

    (void)in_sizes; (void)n_in; (void)out_size;

    cudaFuncSetAttribute(lstm_k, cudaFuncAttributeMaxDynamicSharedMemorySize,
                         LSTM_SM_FLOATS * (int)sizeof(float));

    gemm1_k<<<(NN + 63) / 64, 256>>>(x, Wp, Wsk, asrc, atrg,
                                     wihb, whhb, bihb, bhhb, out);
    {
        dim3 g((NN + 63) / 64, 2);
        p2_k<<<g, 256>>>();
    }
    sortf_k<<<(NN + 255) / 256, 256>>>(ei);
    lstm_k<<<(NN + 63) / 64, 512, LSTM_SM_FLOATS * (int)sizeof(float)>>>(bias, out);
}

// round 15
// speedup vs baseline: 1.0001x; 1.0001x over previous
#include <cuda_runtime.h>
#include <math.h>

// ---------------- problem constants ----------------
#define NN    50000
#define FIN   256
#define FOUT  128
#define HH    128
#define DD    16
#define EE    (NN*DD)     // 800000
#define G4    512         // 4*H

// ---------------- scratch ----------------
__device__ float    g_proj[(size_t)NN*FOUT];   // 25.6MB
__device__ float    g_P2[(size_t)NN*G4];       // 102.4MB  P2 = proj @ w_ih^T (permuted cols)
__device__ float    g_ssrc[NN];
__device__ float    g_strg[NN];
__device__ int      g_seqsrc[EE];
__device__ float    g_seqatt[EE];
__device__ float    g_wih_p[G4*HH];            // permuted w_ih  [512 rows][128]
__device__ float    g_whh_pT[HH*G4];           // permuted w_hh  [128 k][512 cols] K-major
__device__ float    g_bcat[G4];

// ---------------- helpers ----------------
__device__ __forceinline__ float tanh_fast(float x) {
    float r;
    asm("tanh.approx.f32 %0, %1;" : "=f"(r) : "f"(x));
    return r;
}
__device__ __forceinline__ float sig_fast(float x) {
    return fmaf(tanh_fast(0.5f * x), 0.5f, 0.5f);
}
// packed f32x2 ops (Blackwell sm_103a)
typedef unsigned long long ull;
__device__ __forceinline__ ull pack2(float x, float y) {
    ull r; asm("mov.b64 %0, {%1,%2};" : "=l"(r) : "f"(x), "f"(y)); return r;
}
__device__ __forceinline__ float2 unpack2(ull v) {
    float2 r; asm("mov.b64 {%0,%1}, %2;" : "=f"(r.x), "=f"(r.y) : "l"(v)); return r;
}
__device__ __forceinline__ ull ffma2_(ull a, ull b, ull c) {
    ull d; asm("fma.rn.f32x2 %0, %1, %2, %3;" : "=l"(d) : "l"(a), "l"(b), "l"(c)); return d;
}
__device__ __forceinline__ ull add2_(ull a, ull b) {
    ull d; asm("add.rn.f32x2 %0, %1, %2;" : "=l"(d) : "l"(a), "l"(b)); return d;
}
// cp.async helpers
__device__ __forceinline__ void cp16(unsigned dst, const void* src) {
    asm volatile("cp.async.ca.shared.global [%0], [%1], 16;" :: "r"(dst), "l"(src));
}
__device__ __forceinline__ void cp_commit() { asm volatile("cp.async.commit_group;"); }
template <int N>
__device__ __forceinline__ void cp_wait() { asm volatile("cp.async.wait_group %0;" :: "n"(N)); }

// ---------------- kernel 1: prep + proj/skip GEMM + attention dots (fused) -------
__global__ __launch_bounds__(256) void gemm1_k(const float* __restrict__ x,
                                               const float* __restrict__ Wp,
                                               const float* __restrict__ Wsk,
                                               const float* __restrict__ asrc,
                                               const float* __restrict__ atrg,
                                               const float* __restrict__ wih,
                                               const float* __restrict__ whh,
                                               const float* __restrict__ bih,
                                               const float* __restrict__ bhh,
                                               float* __restrict__ out) {
    __shared__ float xs2[32 * 66];    // [kk][row] transposed, pad 2
    __shared__ float ws[256 * 33];    // [col][kk]
    int tid = threadIdx.x, lane = tid & 31, wrp = tid >> 5;
    int n0 = blockIdx.x * 64;

    // fused weight prep (one idx per thread in blocks 0..255)
    if (blockIdx.x < 256) {
        int idx = blockIdx.x * 256 + tid;   // 0..65535
        int R = idx >> 7;
        int k = idx & 127;
        int ch = R >> 7, c = R & 127;
        int gate = c >> 5, dd = c & 31;
        int grow = gate * 128 + ch * 32 + dd;
        g_wih_p[R * 128 + k]  = wih[grow * 128 + k];
        g_whh_pT[k * 512 + R] = whh[grow * 128 + k];
        if (k == 0) g_bcat[R] = bih[grow] + bhh[grow];
    }

    ull accp[4][8];
#pragma unroll
    for (int rp = 0; rp < 4; rp++)
#pragma unroll
        for (int j = 0; j < 8; j++) accp[rp][j] = 0ull;

    for (int k0 = 0; k0 < 256; k0 += 32) {
        __syncthreads();
#pragma unroll
        for (int v = 0; v < 8; v++) {
            int idx = tid + v * 256;
            int r = idx >> 5, kk = idx & 31;
            int n = n0 + r;
            xs2[kk * 66 + r] = (n < NN) ? x[(size_t)n * 256 + k0 + kk] : 0.0f;
        }
#pragma unroll
        for (int v = 0; v < 32; v++) {
            int idx = tid + v * 256;
            int c = idx >> 5, kk = idx & 31;
            ws[c * 33 + kk] = (c < 128) ? Wp[c * 256 + k0 + kk]
                                        : Wsk[(c - 128) * 256 + k0 + kk];
        }
        __syncthreads();
#pragma unroll 4
        for (int kk = 0; kk < 32; kk++) {
            ull uvp[4], wvp[8];
#pragma unroll
            for (int rp = 0; rp < 4; rp++) {
                float2 u2 = *(const float2*)(xs2 + kk * 66 + wrp * 8 + 2 * rp);
                uvp[rp] = pack2(u2.x, u2.y);
            }
#pragma unroll
            for (int j = 0; j < 8; j++) {
                float wv = ws[(j * 32 + lane) * 33 + kk];
                wvp[j] = pack2(wv, wv);
            }
#pragma unroll
            for (int rp = 0; rp < 4; rp++)
#pragma unroll
                for (int j = 0; j < 8; j++)
                    accp[rp][j] = ffma2_(uvp[rp], wvp[j], accp[rp][j]);
        }
    }

    // store proj/skip
#pragma unroll
    for (int rp = 0; rp < 4; rp++) {
        int n = n0 + wrp * 8 + 2 * rp;
#pragma unroll
        for (int j = 0; j < 8; j++) {
            float2 res = unpack2(accp[rp][j]);
            int c = j * 32 + lane;
            if (n < NN) {
                if (c < 128) g_proj[(size_t)n * 128 + c] = res.x;
                else         out[(size_t)n * 128 + (c - 128)] = res.x;
            }
            if (n + 1 < NN) {
                if (c < 128) g_proj[(size_t)(n + 1) * 128 + c] = res.y;
                else         out[(size_t)(n + 1) * 128 + (c - 128)] = res.y;
            }
        }
    }

    // fused attention dots: s_src/s_trg for the 8 rows (4 packed row-pairs)
    ull s1p[4], s2p[4];
#pragma unroll
    for (int rp = 0; rp < 4; rp++) { s1p[rp] = 0ull; s2p[rp] = 0ull; }
#pragma unroll
    for (int j = 0; j < 4; j++) {            // proj cols only (j*32+lane < 128)
        int c = j * 32 + lane;
        float av = asrc[c], tv = atrg[c];
        ull avp = pack2(av, av);
        ull tvp = pack2(tv, tv);
#pragma unroll
        for (int rp = 0; rp < 4; rp++) {
            s1p[rp] = ffma2_(accp[rp][j], avp, s1p[rp]);
            s2p[rp] = ffma2_(accp[rp][j], tvp, s2p[rp]);
        }
    }
#pragma unroll
    for (int rp = 0; rp < 4; rp++) {
#pragma unroll
        for (int o = 16; o; o >>= 1) {
            s1p[rp] = add2_(s1p[rp], __shfl_xor_sync(0xffffffffu, s1p[rp], o));
            s2p[rp] = add2_(s2p[rp], __shfl_xor_sync(0xffffffffu, s2p[rp], o));
        }
        if (lane == 0) {
            float2 v1 = unpack2(s1p[rp]);
            float2 v2 = unpack2(s2p[rp]);
            int n = n0 + wrp * 8 + 2 * rp;
            if (n < NN)     { g_ssrc[n] = v1.x;     g_strg[n] = v2.x; }
            if (n + 1 < NN) { g_ssrc[n + 1] = v1.y; g_strg[n + 1] = v2.y; }
        }
    }
}

// ---------------- kernel 2: P2 = proj @ w_ih_p^T (FFMA2, row-paired, K=128) ------
__global__ __launch_bounds__(256) void p2_k() {
    __shared__ float xs2[32 * 66];
    __shared__ float ws[256 * 33];
    int tid = threadIdx.x, lane = tid & 31, wrp = tid >> 5;
    int n0 = blockIdx.x * 64;
    int coff = blockIdx.y * 256;
    ull accp[4][8];
#pragma unroll
    for (int rp = 0; rp < 4; rp++)
#pragma unroll
        for (int j = 0; j < 8; j++) accp[rp][j] = 0ull;

    for (int k0 = 0; k0 < 128; k0 += 32) {
        __syncthreads();
#pragma unroll
        for (int v = 0; v < 8; v++) {
            int idx = tid + v * 256;
            int r = idx >> 5, kk = idx & 31;
            int n = n0 + r;
            xs2[kk * 66 + r] = (n < NN) ? g_proj[(size_t)n * 128 + k0 + kk] : 0.0f;
        }
#pragma unroll
        for (int v = 0; v < 32; v++) {
            int idx = tid + v * 256;
            int c = idx >> 5, kk = idx & 31;
            ws[c * 33 + kk] = g_wih_p[(coff + c) * 128 + k0 + kk];
        }
        __syncthreads();
#pragma unroll 4
        for (int kk = 0; kk < 32; kk++) {
            ull uvp[4], wvp[8];
#pragma unroll
            for (int rp = 0; rp < 4; rp++) {
                float2 u2 = *(const float2*)(xs2 + kk * 66 + wrp * 8 + 2 * rp);
                uvp[rp] = pack2(u2.x, u2.y);
            }
#pragma unroll
            for (int j = 0; j < 8; j++) {
                float wv = ws[(j * 32 + lane) * 33 + kk];
                wvp[j] = pack2(wv, wv);
            }
#pragma unroll
            for (int rp = 0; rp < 4; rp++)
#pragma unroll
                for (int j = 0; j < 8; j++)
                    accp[rp][j] = ffma2_(uvp[rp], wvp[j], accp[rp][j]);
        }
    }
#pragma unroll
    for (int rp = 0; rp < 4; rp++) {
        int n = n0 + wrp * 8 + 2 * rp;
#pragma unroll
        for (int j = 0; j < 8; j++) {
            float2 res = unpack2(accp[rp][j]);
            int c = coff + j * 32 + lane;
            if (n < NN)     g_P2[(size_t)n * 512 + c] = res.x;
            if (n + 1 < NN) g_P2[(size_t)(n + 1) * 512 + c] = res.y;
        }
    }
}

// ---------------- kernel 3: fused scores + softmax (per-node max) + sort ---------
__global__ void sortf_k(const int* __restrict__ ei) {
    int n = blockIdx.x * blockDim.x + threadIdx.x;
    if (n >= NN) return;
    int srcs[DD];
    float ev[DD], srt[DD];
    int idx[DD];
    float mx = -1e30f;
#pragma unroll
    for (int j = 0; j < DD; j++) {
        int e = n * DD + j;
        int s = ei[e];
        int t = ei[EE + e];
        srcs[j] = s;
        float v = g_ssrc[s] + g_strg[t];
        v = (v >= 0.0f) ? v : 0.2f * v;
        ev[j] = v;
        mx = fmaxf(mx, v);
    }
    float denom = 0.0f;
#pragma unroll
    for (int j = 0; j < DD; j++) {
        float e = expf(ev[j] - mx);
        ev[j] = e;
        denom += e;
    }
    denom += 1e-16f;
    for (int j = 0; j < DD; j++) {
        float key = ev[j];
        int pos = j;
        while (pos > 0 && srt[pos - 1] <= key) {
            srt[pos] = srt[pos - 1];
            idx[pos] = idx[pos - 1];
            pos--;
        }
        srt[pos] = key;
        idx[pos] = j;
    }
    float inv = 1.0f / denom;
#pragma unroll
    for (int t = 0; t < DD; t++) {
        g_seqsrc[n * DD + t] = srcs[idx[t]];
        g_seqatt[n * DD + t] = srt[t] * inv;
    }
}

// ---------------- kernel 4: backward LSTM, 512 threads / 16 warps -----------------
// Same aggregate traffic as the 256-thread version, but 4 warps/SMSP for latency
// hiding. Warp w: rows (w&7)*8..+8, chunks {2*(w>>3)+hl}. Each thread owns one
// dim-pair x all 4 gates -> accp[8][4], c in registers (creg2[8]).
// Continuous cross-timestep weight ring (2 buffers); seq data preloaded.
#define U_STR 132
#define KT 32
#define W_STR 520
#define LSTM_SM_FLOATS (64*U_STR + 2*KT*W_STR + 2*64*DD + 32)

__global__ __launch_bounds__(512, 1) void lstm_k(const float* __restrict__ bias,
                                                 float* __restrict__ out) {
    extern __shared__ float sm[];
    float* u    = sm;                          // [64][U_STR] h (in-place)
    float* wsm  = sm + 64 * U_STR;             // [2][KT][W_STR] w tile ring
    float* satt = wsm + 2 * KT * W_STR;        // [DD][64]
    int*   ssrc = (int*)(satt + 64 * DD);      // [DD][64]

    int tid = threadIdx.x, lane = tid & 31, wrp = tid >> 5;
    int rw = wrp & 7;                 // row group
    int chh = wrp >> 3;               // chunk half (0: chunks 0-1, 1: chunks 2-3)
    int hl = lane >> 4, p = lane & 15;
    int chunk = chh * 2 + hl;
    int n0 = blockIdx.x * 64;
    unsigned wsm_s = (unsigned)__cvta_generic_to_shared(wsm);

    // col offsets: gate g -> col = chunk*128 + g*32 + 2p
    int co[4];
#pragma unroll
    for (int g = 0; g < 4; g++) co[g] = chunk * 128 + g * 32 + 2 * p;

    // bias pairs
    ull bcp[4];
#pragma unroll
    for (int g = 0; g < 4; g++) {
        float2 b2 = *(const float2*)(g_bcat + co[g]);
        bcp[g] = pack2(b2.x, b2.y);
    }

    // cell state: creg2[row] = c for dims chunk*32 + {2p,2p+1}
    float2 creg2[8];
#pragma unroll
    for (int i = 0; i < 8; i++) creg2[i] = make_float2(0.0f, 0.0f);

    // preload ALL timesteps' seq data: layout [t][node]
#pragma unroll
    for (int v = 0; v < 2; v++) {
        int idx = tid + v * 512;             // 0..1023 = node*16 + t
        int node = idx >> 4, t = idx & 15;
        int n = n0 + node;
        if (n < NN) {
            ssrc[t * 64 + node] = g_seqsrc[n * DD + t];
            satt[t * 64 + node] = g_seqatt[n * DD + t];
        } else {
            ssrc[t * 64 + node] = 0;
            satt[t * 64 + node] = 0.0f;
        }
    }

    // weight ring prologue: issue tiles 0 and 1 (own commit groups)
#pragma unroll
    for (int tile = 0; tile < 2; tile++) {
        unsigned db = wsm_s + ((tile & 1) * KT * W_STR) * 4;
#pragma unroll
        for (int v = 0; v < 8; v++) {
            int f4 = tid + v * 512;
            int kk = f4 >> 7, c4 = f4 & 127;
            cp16(db + (kk * W_STR + c4 * 4) * 4,
                 g_whh_pT + (size_t)(tile * KT + kk) * 512 + c4 * 4);
        }
        cp_commit();
    }
    __syncthreads();   // seq data visible

#pragma unroll 1
    for (int t = 0; t < DD; t++) {
        ull accp[8][4];
#pragma unroll
        for (int i = 0; i < 8; i++)
#pragma unroll
            for (int g = 0; g < 4; g++) accp[i][g] = 0ull;

        if (t > 0) {
#pragma unroll 1
            for (int kt = 0; kt < 4; kt++) {
                cp_wait<1>();          // tile kt has landed (issued >=2 phases ago)
                __syncthreads();

                const float* wb = wsm + (kt & 1) * KT * W_STR;
                const float* ub = u + kt * KT;
#pragma unroll 4
                for (int kk2 = 0; kk2 < KT / 2; kk2++) {
                    float2 uk[8];
#pragma unroll
                    for (int i = 0; i < 8; i++)
                        uk[i] = *(const float2*)(ub + (rw * 8 + i) * U_STR + 2 * kk2);
#pragma unroll
                    for (int sub = 0; sub < 2; sub++) {
                        ull wvp[4];
#pragma unroll
                        for (int g = 0; g < 4; g++) {
                            float2 w2 = *(const float2*)(wb + (2 * kk2 + sub) * W_STR + co[g]);
                            wvp[g] = pack2(w2.x, w2.y);
                        }
#pragma unroll
                        for (int i = 0; i < 8; i++) {
                            float us = sub ? uk[i].y : uk[i].x;
                            ull up = pack2(us, us);
#pragma unroll
                            for (int g = 0; g < 4; g++)
                                accp[i][g] = ffma2_(up, wvp[g], accp[i][g]);
                        }
                    }
                }
                __syncthreads();

                // refill this buffer with the tile needed 2 phases from now
                {
                    int ntile = (kt + 2) & 3;
                    unsigned db = wsm_s + ((kt & 1) * KT * W_STR) * 4;
#pragma unroll
                    for (int v = 0; v < 8; v++) {
                        int f4 = tid + v * 512;
                        int kk = f4 >> 7, c4 = f4 & 127;
                        cp16(db + (kk * W_STR + c4 * 4) * 4,
                             g_whh_pT + (size_t)(ntile * KT + kk) * 512 + c4 * 4);
                    }
                    cp_commit();
                }
            }
        }

        // x-contribution: acc = acc + bias + att * P2[src]  (batched 2 rows)
        const float* sattT = satt + t * 64;
        const int*   ssrcT = ssrc + t * 64;
#pragma unroll
        for (int b = 0; b < 4; b++) {
            ull pvp[2][4];
#pragma unroll
            for (int i2 = 0; i2 < 2; i2++) {
                int s = ssrcT[rw * 8 + b * 2 + i2];
                const float* pp = g_P2 + (size_t)s * 512;
#pragma unroll
                for (int g = 0; g < 4; g++) {
                    float2 v2 = *(const float2*)(pp + co[g]);
                    pvp[i2][g] = pack2(v2.x, v2.y);
                }
            }
#pragma unroll
            for (int i2 = 0; i2 < 2; i2++) {
                int i = b * 2 + i2;
                float a = sattT[rw * 8 + i];
                ull ap = pack2(a, a);
#pragma unroll
                for (int g = 0; g < 4; g++)
                    accp[i][g] = ffma2_(ap, pvp[i2][g], add2_(accp[i][g], bcp[g]));
            }
        }

        // gate activations + c/h update (h written in place; all u reads done)
#pragma unroll
        for (int i = 0; i < 8; i++) {
            float2 iv = unpack2(accp[i][0]);
            float2 fv = unpack2(accp[i][1]);
            float2 gv = unpack2(accp[i][2]);
            float2 ov = unpack2(accp[i][3]);
            float2 cp2 = creg2[i];
            float c0 = fmaf(sig_fast(fv.x), cp2.x, sig_fast(iv.x) * tanh_fast(gv.x));
            float c1 = fmaf(sig_fast(fv.y), cp2.y, sig_fast(iv.y) * tanh_fast(gv.y));
            creg2[i] = make_float2(c0, c1);
            float2 hh = make_float2(sig_fast(ov.x) * tanh_fast(c0),
                                    sig_fast(ov.y) * tanh_fast(c1));
            *(float2*)(u + (rw * 8 + i) * U_STR + chunk * 32 + 2 * p) = hh;
        }
        __syncthreads();
    }

    // epilogue: final h in u
    for (int idx = tid; idx < 64 * 128; idx += 512) {
        int r = idx >> 7, d = idx & 127;
        int n = n0 + r;
        if (n < NN) {
            float v = u[r * U_STR + d] + out[(size_t)n * 128 + d] + bias[d];
            out[(size_t)n * 128 + d] = (v >= 0.0f) ? v : 0.01f * v;
        }
    }
}

// ---------------- launch ----------------
extern "C" void kernel_launch(void* const* d_in, const int* in_sizes, int n_in,
                              void* d_out, int out_size) {
    const float* x    = (const float*)d_in[0];
    const float* Wp   = (const float*)d_in[1];
    const float* asrc = (const float*)d_in[2];
    const float* atrg = (const float*)d_in[3];
    const float* Wsk  = (const float*)d_in[4];
    const float* bias = (const float*)d_in[5];
    // d_in[6..9]: forward-direction weights, unused by the reference
    const float* wihb = (const float*)d_in[10];
    const float* whhb = (const float*)d_in[11];
    const float* bihb = (const float*)d_in[12];
    const float* bhhb = (const float*)d_in[13];
    const int*   ei   = (const int*)d_in[14];
    float* out = (float*)d_out;

    (void)in_sizes; (void)n_in; (void)out_size;

    cudaFuncSetAttribute(lstm_k, cudaFuncAttributeMaxDynamicSharedMemorySize,
                         LSTM_SM_FLOATS * (int)sizeof(float));

    gemm1_k<<<(NN + 63) / 64, 256>>>(x, Wp, Wsk, asrc, atrg,
                                     wihb, whhb, bihb, bhhb, out);
    {
        dim3 g((NN + 63) / 64, 2);
        p2_k<<<g, 256>>>();
    }
    sortf_k<<<(NN + 255) / 256, 256>>>(ei);
    lstm_k<<<(NN + 63) / 64, 512, LSTM_SM_FLOATS * (int)sizeof(float)>>>(bias, out);
}

// round 17
// speedup vs baseline: 1.8277x; 1.8275x over previous
#include <cuda_runtime.h>
#include <cuda_bf16.h>
#include <math.h>

#define NN    50000
#define FIN   256
#define FOUT  128
#define HH    128
#define DD    16
#define EE    (NN*DD)
#define G4    512

// ---------------- scratch ----------------
__device__ float    g_proj[(size_t)NN*FOUT];
__device__ float    g_P2[(size_t)NN*G4];
__device__ float    g_ssrc[NN];
__device__ float    g_strg[NN];
__device__ int      g_seqsrc[EE];
__device__ float    g_seqatt[EE];
__device__ float    g_wih_p[G4*HH];            // permuted w_ih [512][128]
__device__ float    g_bcat[G4];                // permuted bias
// w_hh bf16 hi/lo, per 64-col chunk, pre-swizzled for ldmatrix: [q][hi 16KB | lo 16KB]
__device__ unsigned char g_whh_s[8*32768];

// ---------------- permutation (micro-8) ----------------
// col c: q=c>>6 (chunk), n=c&63: m8=n>>5, gate=(n>>3)&3, d8=n&7
// dim = q*16 + m8*8 + d8 ; original row = gate*128 + dim
__device__ __forceinline__ int grow_of(int c) {
    int q = c >> 6, n = c & 63;
    int m8 = n >> 5, g = (n >> 3) & 3, d8 = n & 7;
    return g * 128 + (q * 16 + m8 * 8 + d8);
}

// ---------------- helpers ----------------
__device__ __forceinline__ float tanh_fast(float x) {
    float r; asm("tanh.approx.f32 %0, %1;" : "=f"(r) : "f"(x)); return r;
}
__device__ __forceinline__ float sig_fast(float x) {
    return fmaf(tanh_fast(0.5f * x), 0.5f, 0.5f);
}
typedef unsigned long long ull;
__device__ __forceinline__ ull pack2(float x, float y) {
    ull r; asm("mov.b64 %0, {%1,%2};" : "=l"(r) : "f"(x), "f"(y)); return r;
}
__device__ __forceinline__ float2 unpack2(ull v) {
    float2 r; asm("mov.b64 {%0,%1}, %2;" : "=f"(r.x), "=f"(r.y) : "l"(v)); return r;
}
__device__ __forceinline__ ull ffma2_(ull a, ull b, ull c) {
    ull d; asm("fma.rn.f32x2 %0, %1, %2, %3;" : "=l"(d) : "l"(a), "l"(b), "l"(c)); return d;
}
__device__ __forceinline__ ull add2_(ull a, ull b) {
    ull d; asm("add.rn.f32x2 %0, %1, %2;" : "=l"(d) : "l"(a), "l"(b)); return d;
}
__device__ __forceinline__ void cp16(unsigned dst, const void* src) {
    asm volatile("cp.async.ca.shared.global [%0], [%1], 16;" :: "r"(dst), "l"(src));
}
__device__ __forceinline__ void cp_commit() { asm volatile("cp.async.commit_group;"); }
template <int N>
__device__ __forceinline__ void cp_wait() { asm volatile("cp.async.wait_group %0;" :: "n"(N)); }

// ---------------- mma / ldmatrix helpers (plain sm_80+ PTX) ----------------
__device__ __forceinline__ void ldsm4(unsigned* r, unsigned a) {
    asm volatile("ldmatrix.sync.aligned.m8n8.x4.shared.b16 {%0,%1,%2,%3}, [%4];"
                 : "=r"(r[0]), "=r"(r[1]), "=r"(r[2]), "=r"(r[3]) : "r"(a));
}
__device__ __forceinline__ void ldsm4t(unsigned* r, unsigned a) {
    asm volatile("ldmatrix.sync.aligned.m8n8.x4.trans.shared.b16 {%0,%1,%2,%3}, [%4];"
                 : "=r"(r[0]), "=r"(r[1]), "=r"(r[2]), "=r"(r[3]) : "r"(a));
}
__device__ __forceinline__ void mma16816(float* d, const unsigned* a,
                                         unsigned b0, unsigned b1) {
    asm volatile(
        "mma.sync.aligned.m16n8k16.row.col.f32.bf16.bf16.f32 "
        "{%0,%1,%2,%3}, {%4,%5,%6,%7}, {%8,%9}, {%0,%1,%2,%3};"
        : "+f"(d[0]), "+f"(d[1]), "+f"(d[2]), "+f"(d[3])
        : "r"(a[0]), "r"(a[1]), "r"(a[2]), "r"(a[3]), "r"(b0), "r"(b1));
}

// ---------------- kernel 0: whh -> bf16 hi/lo, per-chunk ldmatrix-swizzled -------
__global__ void wprep_k(const float* __restrict__ whh) {
    int idx = blockIdx.x * blockDim.x + threadIdx.x;   // 0..65535
    int c = idx >> 7, k = idx & 127;
    float w = whh[grow_of(c) * 128 + k];
    __nv_bfloat16 hi = __float2bfloat16(w);
    __nv_bfloat16 lo = __float2bfloat16(w - __bfloat162float(hi));
    int q = c >> 6, n = c & 63;
    unsigned u = (unsigned)(n >> 3) ^ (unsigned)(k & 7);
    unsigned byteo = (unsigned)k * 128 + u * 16 + (unsigned)(n & 7) * 2;
    *(unsigned short*)(g_whh_s + q * 32768 + byteo) = __bfloat16_as_ushort(hi);
    *(unsigned short*)(g_whh_s + q * 32768 + 16384 + byteo) = __bfloat16_as_ushort(lo);
}

// ---------------- kernel 1: prep + proj/skip GEMM + attention dots ----------------
__global__ __launch_bounds__(256) void gemm1_k(const float* __restrict__ x,
                                               const float* __restrict__ Wp,
                                               const float* __restrict__ Wsk,
                                               const float* __restrict__ asrc,
                                               const float* __restrict__ atrg,
                                               const float* __restrict__ wih,
                                               const float* __restrict__ bih,
                                               const float* __restrict__ bhh,
                                               float* __restrict__ out) {
    __shared__ float xs2[32 * 66];
    __shared__ float ws[256 * 33];
    int tid = threadIdx.x, lane = tid & 31, wrp = tid >> 5;
    int n0 = blockIdx.x * 64;

    if (blockIdx.x < 256) {
        int idx = blockIdx.x * 256 + tid;
        int R = idx >> 7, k = idx & 127;
        int grow = grow_of(R);
        g_wih_p[R * 128 + k] = wih[grow * 128 + k];
        if (k == 0) g_bcat[R] = bih[grow] + bhh[grow];
    }

    ull accp[4][8];
#pragma unroll
    for (int rp = 0; rp < 4; rp++)
#pragma unroll
        for (int j = 0; j < 8; j++) accp[rp][j] = 0ull;

    for (int k0 = 0; k0 < 256; k0 += 32) {
        __syncthreads();
#pragma unroll
        for (int v = 0; v < 8; v++) {
            int idx = tid + v * 256;
            int r = idx >> 5, kk = idx & 31;
            int n = n0 + r;
            xs2[kk * 66 + r] = (n < NN) ? x[(size_t)n * 256 + k0 + kk] : 0.0f;
        }
#pragma unroll
        for (int v = 0; v < 32; v++) {
            int idx = tid + v * 256;
            int c = idx >> 5, kk = idx & 31;
            ws[c * 33 + kk] = (c < 128) ? Wp[c * 256 + k0 + kk]
                                        : Wsk[(c - 128) * 256 + k0 + kk];
        }
        __syncthreads();
#pragma unroll 4
        for (int kk = 0; kk < 32; kk++) {
            ull uvp[4], wvp[8];
#pragma unroll
            for (int rp = 0; rp < 4; rp++) {
                float2 u2 = *(const float2*)(xs2 + kk * 66 + wrp * 8 + 2 * rp);
                uvp[rp] = pack2(u2.x, u2.y);
            }
#pragma unroll
            for (int j = 0; j < 8; j++) {
                float wv = ws[(j * 32 + lane) * 33 + kk];
                wvp[j] = pack2(wv, wv);
            }
#pragma unroll
            for (int rp = 0; rp < 4; rp++)
#pragma unroll
                for (int j = 0; j < 8; j++)
                    accp[rp][j] = ffma2_(uvp[rp], wvp[j], accp[rp][j]);
        }
    }
#pragma unroll
    for (int rp = 0; rp < 4; rp++) {
        int n = n0 + wrp * 8 + 2 * rp;
#pragma unroll
        for (int j = 0; j < 8; j++) {
            float2 res = unpack2(accp[rp][j]);
            int c = j * 32 + lane;
            if (n < NN) {
                if (c < 128) g_proj[(size_t)n * 128 + c] = res.x;
                else         out[(size_t)n * 128 + (c - 128)] = res.x;
            }
            if (n + 1 < NN) {
                if (c < 128) g_proj[(size_t)(n + 1) * 128 + c] = res.y;
                else         out[(size_t)(n + 1) * 128 + (c - 128)] = res.y;
            }
        }
    }
    ull s1p[4], s2p[4];
#pragma unroll
    for (int rp = 0; rp < 4; rp++) { s1p[rp] = 0ull; s2p[rp] = 0ull; }
#pragma unroll
    for (int j = 0; j < 4; j++) {
        int c = j * 32 + lane;
        float av = asrc[c], tv = atrg[c];
        ull avp = pack2(av, av), tvp = pack2(tv, tv);
#pragma unroll
        for (int rp = 0; rp < 4; rp++) {
            s1p[rp] = ffma2_(accp[rp][j], avp, s1p[rp]);
            s2p[rp] = ffma2_(accp[rp][j], tvp, s2p[rp]);
        }
    }
#pragma unroll
    for (int rp = 0; rp < 4; rp++) {
#pragma unroll
        for (int o = 16; o; o >>= 1) {
            s1p[rp] = add2_(s1p[rp], __shfl_xor_sync(0xffffffffu, s1p[rp], o));
            s2p[rp] = add2_(s2p[rp], __shfl_xor_sync(0xffffffffu, s2p[rp], o));
        }
        if (lane == 0) {
            float2 v1 = unpack2(s1p[rp]);
            float2 v2 = unpack2(s2p[rp]);
            int n = n0 + wrp * 8 + 2 * rp;
            if (n < NN)     { g_ssrc[n] = v1.x;     g_strg[n] = v2.x; }
            if (n + 1 < NN) { g_ssrc[n + 1] = v1.y; g_strg[n + 1] = v2.y; }
        }
    }
}

// ---------------- kernel 2: P2 = proj @ w_ih_p^T ----------------
__global__ __launch_bounds__(256) void p2_k() {
    __shared__ float xs2[32 * 66];
    __shared__ float ws[256 * 33];
    int tid = threadIdx.x, lane = tid & 31, wrp = tid >> 5;
    int n0 = blockIdx.x * 64;
    int coff = blockIdx.y * 256;
    ull accp[4][8];
#pragma unroll
    for (int rp = 0; rp < 4; rp++)
#pragma unroll
        for (int j = 0; j < 8; j++) accp[rp][j] = 0ull;

    for (int k0 = 0; k0 < 128; k0 += 32) {
        __syncthreads();
#pragma unroll
        for (int v = 0; v < 8; v++) {
            int idx = tid + v * 256;
            int r = idx >> 5, kk = idx & 31;
            int n = n0 + r;
            xs2[kk * 66 + r] = (n < NN) ? g_proj[(size_t)n * 128 + k0 + kk] : 0.0f;
        }
#pragma unroll
        for (int v = 0; v < 32; v++) {
            int idx = tid + v * 256;
            int c = idx >> 5, kk = idx & 31;
            ws[c * 33 + kk] = g_wih_p[(coff + c) * 128 + k0 + kk];
        }
        __syncthreads();
#pragma unroll 4
        for (int kk = 0; kk < 32; kk++) {
            ull uvp[4], wvp[8];
#pragma unroll
            for (int rp = 0; rp < 4; rp++) {
                float2 u2 = *(const float2*)(xs2 + kk * 66 + wrp * 8 + 2 * rp);
                uvp[rp] = pack2(u2.x, u2.y);
            }
#pragma unroll
            for (int j = 0; j < 8; j++) {
                float wv = ws[(j * 32 + lane) * 33 + kk];
                wvp[j] = pack2(wv, wv);
            }
#pragma unroll
            for (int rp = 0; rp < 4; rp++)
#pragma unroll
                for (int j = 0; j < 8; j++)
                    accp[rp][j] = ffma2_(uvp[rp], wvp[j], accp[rp][j]);
        }
    }
#pragma unroll
    for (int rp = 0; rp < 4; rp++) {
        int n = n0 + wrp * 8 + 2 * rp;
#pragma unroll
        for (int j = 0; j < 8; j++) {
            float2 res = unpack2(accp[rp][j]);
            int c = coff + j * 32 + lane;
            if (n < NN)     g_P2[(size_t)n * 512 + c] = res.x;
            if (n + 1 < NN) g_P2[(size_t)(n + 1) * 512 + c] = res.y;
        }
    }
}

// ---------------- kernel 3: scores + softmax + sort ----------------
__global__ void sortf_k(const int* __restrict__ ei) {
    int n = blockIdx.x * blockDim.x + threadIdx.x;
    if (n >= NN) return;
    int srcs[DD];
    float ev[DD], srt[DD];
    int idx[DD];
    float mx = -1e30f;
#pragma unroll
    for (int j = 0; j < DD; j++) {
        int e = n * DD + j;
        int s = ei[e], t = ei[EE + e];
        srcs[j] = s;
        float v = g_ssrc[s] + g_strg[t];
        v = (v >= 0.0f) ? v : 0.2f * v;
        ev[j] = v;
        mx = fmaxf(mx, v);
    }
    float denom = 0.0f;
#pragma unroll
    for (int j = 0; j < DD; j++) {
        float e = expf(ev[j] - mx);
        ev[j] = e;
        denom += e;
    }
    denom += 1e-16f;
    for (int j = 0; j < DD; j++) {
        float key = ev[j];
        int pos = j;
        while (pos > 0 && srt[pos - 1] <= key) {
            srt[pos] = srt[pos - 1];
            idx[pos] = idx[pos - 1];
            pos--;
        }
        srt[pos] = key;
        idx[pos] = j;
    }
    float inv = 1.0f / denom;
#pragma unroll
    for (int t = 0; t < DD; t++) {
        g_seqsrc[n * DD + t] = srcs[idx[t]];
        g_seqatt[n * DD + t] = srt[t] * inv;
    }
}

// ---------------- kernel 4: mma.sync bf16-split LSTM ----------------
// 128 nodes/block, 256 threads, 8 warps = 4(M=32) x 2(N=32).
// Per timestep: 8 passes over 64-col chunks; per warp: 2 m-tiles x 4 n-tiles x
// 8 k-steps x 3 split-terms of m16n8k16. h bf16 hi/lo in double-buffered SMEM;
// W streamed via 2x32KB cp.async ring (chunk q <-> buf q&1, lead-1 refill).
// SMEM: Wring 64KB | A 2x(hi32+lo32)=128KB | satt 8KB | ssrc 8KB  (+1KB align)
#define LSTM_SMEM_REQ (65536 + 131072 + 16384 + 1024)

__global__ __launch_bounds__(256, 1) void lstm_mma_k(const float* __restrict__ bias,
                                                     float* __restrict__ out) {
    extern __shared__ char smraw[];
    unsigned base;
    asm("{ .reg .u64 t; cvta.to.shared.u64 t, %1; cvt.u32.u64 %0, t; }" : "=r"(base) : "l"(smraw));
    unsigned al = (base + 1023u) & ~1023u;
    char* sm0 = smraw + (al - base);
    const unsigned WRING = al;                 // 2 x 32KB
    const unsigned ABUF  = al + 65536;         // 2 x 64KB (hi 32 | lo 32)
    float* satt_p = (float*)(sm0 + 196608);    // [16][128]
    int*   ssrc_p = (int*)(sm0 + 204800);      // [16][128]

    int tid = threadIdx.x, lane = tid & 31, wrp = tid >> 5;
    int Wn = wrp & 1, Mr = wrp >> 1;
    int tg = lane >> 2, t4 = lane & 3, l15 = lane & 15, lsw = lane & 7, kse = lane >> 4;
    int n0 = blockIdx.x * 128;

    // A-frag per-lane row offsets (row = Mr*32 + mt*16 + l15)
    unsigned rowA[2];
#pragma unroll
    for (int mt = 0; mt < 2; mt++) rowA[mt] = (unsigned)(Mr * 32 + mt * 16 + l15) * 256;
    // W-frag per-lane swizzled col-unit offsets
    unsigned cuX[2];
#pragma unroll
    for (int np = 0; np < 2; np++)
        cuX[np] = (unsigned)(((Wn * 4 + 2 * np + kse) ^ lsw) << 4);

    // seq preload [t][node]
#pragma unroll
    for (int v = 0; v < 8; v++) {
        int idx = tid + v * 256;           // 0..2047
        int node = idx & 127, tt = idx >> 7;
        int n = n0 + node;
        if (n < NN) {
            ssrc_p[tt * 128 + node] = g_seqsrc[n * DD + tt];
            satt_p[tt * 128 + node] = g_seqatt[n * DD + tt];
        } else {
            ssrc_p[tt * 128 + node] = 0;
            satt_p[tt * 128 + node] = 0.0f;
        }
    }
    // W prologue: chunk 0 -> buf 0
#pragma unroll
    for (int v = 0; v < 8; v++) {
        int u = tid + v * 256;             // 16B units, 0..2047
        cp16(WRING + (unsigned)u * 16, g_whh_s + u * 16);
    }
    cp_commit();
    __syncthreads();

    float cst[8][8];                       // c state: [pass][ri*2+delta]
#pragma unroll
    for (int q = 0; q < 8; q++)
#pragma unroll
        for (int j = 0; j < 8; j++) cst[q][j] = 0.0f;

#pragma unroll 1
    for (int t = 0; t < DD; t++) {
        unsigned Ard = ABUF + (unsigned)(t & 1) * 65536;
        unsigned Awr = ABUF + (unsigned)((t + 1) & 1) * 65536;

#pragma unroll
        for (int q = 0; q < 8; q++) {
            if (t > 0) {
                cp_wait<0>();
                __syncthreads();
                // lead-1 refill: chunk (q+1)&7 -> buf (q+1)&1 (consumed last pass)
                if (!(t == DD - 1 && q == 7)) {
                    int nq = (q + 1) & 7;
                    unsigned db = WRING + (unsigned)((q + 1) & 1) * 32768;
#pragma unroll
                    for (int v = 0; v < 8; v++) {
                        int u = tid + v * 256;
                        cp16(db + (unsigned)u * 16, g_whh_s + nq * 32768 + u * 16);
                    }
                    cp_commit();
                }
            }

            // prefetch x-gather + bias
            float2 pv[4][4];
            float  av[4];
            int    lrow[4];
#pragma unroll
            for (int ri = 0; ri < 4; ri++) {
                int lr = Mr * 32 + (ri >> 1) * 16 + tg + (ri & 1) * 8;
                lrow[ri] = lr;
                int s = ssrc_p[t * 128 + lr];
                av[ri] = satt_p[t * 128 + lr];
                const float* pp = g_P2 + (size_t)s * 512 + q * 64 + Wn * 32 + 2 * t4;
#pragma unroll
                for (int nt = 0; nt < 4; nt++)
                    pv[ri][nt] = __ldg((const float2*)(pp + nt * 8));
            }
            float2 bv[4];
#pragma unroll
            for (int nt = 0; nt < 4; nt++)
                bv[nt] = __ldg((const float2*)(g_bcat + q * 64 + Wn * 32 + nt * 8 + 2 * t4));

            float acc[2][4][4];
#pragma unroll
            for (int mt = 0; mt < 2; mt++)
#pragma unroll
                for (int nt = 0; nt < 4; nt++)
#pragma unroll
                    for (int j = 0; j < 4; j++) acc[mt][nt][j] = 0.0f;

            if (t > 0) {
                unsigned Wb = WRING + (unsigned)(q & 1) * 32768;
#pragma unroll 1
                for (int ks = 0; ks < 8; ks++) {
                    unsigned ahi[2][4], alo[2][4];
                    unsigned ua = ((unsigned)(2 * ks + kse) ^ (unsigned)lsw) << 4;
#pragma unroll
                    for (int mt = 0; mt < 2; mt++) {
                        ldsm4(ahi[mt], Ard + rowA[mt] + ua);
                        ldsm4(alo[mt], Ard + 32768 + rowA[mt] + ua);
                    }
                    unsigned bh[2][4], bl[2][4];
                    unsigned krow = (unsigned)(ks * 16 + l15) * 128;
#pragma unroll
                    for (int np = 0; np < 2; np++) {
                        ldsm4t(bh[np], Wb + krow + cuX[np]);
                        ldsm4t(bl[np], Wb + 16384 + krow + cuX[np]);
                    }
#pragma unroll
                    for (int mt = 0; mt < 2; mt++)
#pragma unroll
                        for (int np = 0; np < 2; np++)
#pragma unroll
                            for (int j = 0; j < 2; j++) {
                                int nt = np * 2 + j;
                                mma16816(acc[mt][nt], ahi[mt], bh[np][j * 2], bh[np][j * 2 + 1]);
                                mma16816(acc[mt][nt], alo[mt], bh[np][j * 2], bh[np][j * 2 + 1]);
                                mma16816(acc[mt][nt], ahi[mt], bl[np][j * 2], bl[np][j * 2 + 1]);
                            }
                }
            }

            // activation: per row, gates i/f/g/o = n-tiles 0..3, dims d8 = 2t4+{0,1}
#pragma unroll
            for (int ri = 0; ri < 4; ri++) {
                int mt = ri >> 1, h8 = ri & 1;
                float a = av[ri];
                float hvv[2];
#pragma unroll
                for (int dl = 0; dl < 2; dl++) {
                    float gi = fmaf(a, dl ? pv[ri][0].y : pv[ri][0].x,
                                    acc[mt][0][h8 * 2 + dl] + (dl ? bv[0].y : bv[0].x));
                    float gf = fmaf(a, dl ? pv[ri][1].y : pv[ri][1].x,
                                    acc[mt][1][h8 * 2 + dl] + (dl ? bv[1].y : bv[1].x));
                    float gg = fmaf(a, dl ? pv[ri][2].y : pv[ri][2].x,
                                    acc[mt][2][h8 * 2 + dl] + (dl ? bv[2].y : bv[2].x));
                    float go = fmaf(a, dl ? pv[ri][3].y : pv[ri][3].x,
                                    acc[mt][3][h8 * 2 + dl] + (dl ? bv[3].y : bv[3].x));
                    float cn = fmaf(sig_fast(gf), cst[q][ri * 2 + dl],
                                    sig_fast(gi) * tanh_fast(gg));
                    cst[q][ri * 2 + dl] = cn;
                    hvv[dl] = sig_fast(go) * tanh_fast(cn);
                }
                if (t < DD - 1) {
                    __nv_bfloat16 h0 = __float2bfloat16(hvv[0]);
                    __nv_bfloat16 h1 = __float2bfloat16(hvv[1]);
                    __nv_bfloat16 l0 = __float2bfloat16(hvv[0] - __bfloat162float(h0));
                    __nv_bfloat16 l1 = __float2bfloat16(hvv[1] - __bfloat162float(h1));
                    unsigned hw = (unsigned)lrow[ri] * 256 +
                                  ((unsigned)((q * 2 + Wn) ^ tg) << 4) + (unsigned)t4 * 4;
                    *(unsigned*)(sm0 + (Awr - al) + hw) =
                        (unsigned)__bfloat16_as_ushort(h0) |
                        ((unsigned)__bfloat16_as_ushort(h1) << 16);
                    *(unsigned*)(sm0 + (Awr - al) + 32768 + hw) =
                        (unsigned)__bfloat16_as_ushort(l0) |
                        ((unsigned)__bfloat16_as_ushort(l1) << 16);
                } else {
                    int node = n0 + lrow[ri];
                    if (node < NN) {
                        int gd = q * 16 + Wn * 8 + 2 * t4;
                        float* op = out + (size_t)node * 128 + gd;
                        float2 bb = __ldg((const float2*)(bias + gd));
                        float v0 = hvv[0] + op[0] + bb.x;
                        float v1 = hvv[1] + op[1] + bb.y;
                        op[0] = (v0 >= 0.0f) ? v0 : 0.01f * v0;
                        op[1] = (v1 >= 0.0f) ? v1 : 0.01f * v1;
                    }
                }
            }
        }
    }
}

// ---------------- launch ----------------
extern "C" void kernel_launch(void* const* d_in, const int* in_sizes, int n_in,
                              void* d_out, int out_size) {
    const float* x    = (const float*)d_in[0];
    const float* Wp   = (const float*)d_in[1];
    const float* asrc = (const float*)d_in[2];
    const float* atrg = (const float*)d_in[3];
    const float* Wsk  = (const float*)d_in[4];
    const float* bias = (const float*)d_in[5];
    const float* wihb = (const float*)d_in[10];
    const float* whhb = (const float*)d_in[11];
    const float* bihb = (const float*)d_in[12];
    const float* bhhb = (const float*)d_in[13];
    const int*   ei   = (const int*)d_in[14];
    float* out = (float*)d_out;
    (void)in_sizes; (void)n_in; (void)out_size;

    cudaFuncSetAttribute(lstm_mma_k, cudaFuncAttributeMaxDynamicSharedMemorySize,
                         LSTM_SMEM_REQ);

    gemm1_k<<<(NN + 63) / 64, 256>>>(x, Wp, Wsk, asrc, atrg, wihb, bihb, bhhb, out);
    wprep_k<<<256, 256>>>(whhb);
    {
        dim3 g((NN + 63) / 64, 2);
        p2_k<<<g, 256>>>();
    }
    sortf_k<<<(NN + 255) / 256, 256>>>(ei);
    lstm_mma_k<<<(NN + 127) / 128, 256, LSTM_SMEM_REQ>>>(bias, out);
}